// round 8
// baseline (speedup 1.0000x reference)
#include <cuda_runtime.h>
#include <cstdint>

// Batched negative-Pearson loss. Half-row per CTA for fine-grained drain.
// preds, labels: [B, N] fp32, B=4096, N=8192. out = mean_b(1 - pearson_b).
//
// CTA (row, half) computes 5 partial sums over N/2 elements -> disjoint
// slot g_part[row][half][5]. Second CTA to finish a row (per-row ticket)
// combines halves in FIXED order (deterministic), writes row loss, resets
// its ticket, bumps global ticket. Last row-winner reduces all row losses.

#define ROW_N 8192
#define HALF_N (ROW_N / 2)
#define MAX_B 4096
#define TPB   256
#define V4_PER_THREAD ((HALF_N / 4) / TPB) // 4

__device__ float g_part[MAX_B][2][5];
__device__ float g_row_loss[MAX_B];
__device__ unsigned int g_row_ticket[MAX_B]; // zero-init; self-resetting
__device__ unsigned int g_ticket;            // zero-init; self-resetting

__device__ __forceinline__ float warp_sum(float v) {
    #pragma unroll
    for (int off = 16; off > 0; off >>= 1)
        v += __shfl_down_sync(0xffffffffu, v, off);
    return v;
}

__device__ __forceinline__ float4 ldcs4(const float4* p) {
    float4 r;
    asm volatile("ld.global.cs.v4.f32 {%0,%1,%2,%3}, [%4];"
                 : "=f"(r.x), "=f"(r.y), "=f"(r.z), "=f"(r.w)
                 : "l"(p));
    return r;
}

__device__ __forceinline__ float ldcg(const float* p) {
    float r;
    asm volatile("ld.global.cg.f32 %0, [%1];" : "=f"(r) : "l"(p));
    return r;
}

__global__ __launch_bounds__(TPB, 8)
void np_half_kernel(const float* __restrict__ preds,
                    const float* __restrict__ labels,
                    float* __restrict__ out, int B) {
    const int row  = blockIdx.x >> 1;
    const int half = blockIdx.x & 1;
    const size_t base = (size_t)row * ROW_N + (size_t)half * HALF_N;
    const float4* __restrict__ p = reinterpret_cast<const float4*>(preds + base);
    const float4* __restrict__ l = reinterpret_cast<const float4*>(labels + base);

    float sx = 0.f, sy = 0.f, sxy = 0.f, sxx = 0.f, syy = 0.f;

    float4 a[V4_PER_THREAD], b[V4_PER_THREAD];
    #pragma unroll
    for (int k = 0; k < V4_PER_THREAD; k++) a[k] = ldcs4(p + threadIdx.x + k * TPB);
    #pragma unroll
    for (int k = 0; k < V4_PER_THREAD; k++) b[k] = ldcs4(l + threadIdx.x + k * TPB);

    #pragma unroll
    for (int k = 0; k < V4_PER_THREAD; k++) {
        sx  += a[k].x + a[k].y + a[k].z + a[k].w;
        sy  += b[k].x + b[k].y + b[k].z + b[k].w;
        sxy = fmaf(a[k].x, b[k].x, sxy); sxy = fmaf(a[k].y, b[k].y, sxy);
        sxy = fmaf(a[k].z, b[k].z, sxy); sxy = fmaf(a[k].w, b[k].w, sxy);
        sxx = fmaf(a[k].x, a[k].x, sxx); sxx = fmaf(a[k].y, a[k].y, sxx);
        sxx = fmaf(a[k].z, a[k].z, sxx); sxx = fmaf(a[k].w, a[k].w, sxx);
        syy = fmaf(b[k].x, b[k].x, syy); syy = fmaf(b[k].y, b[k].y, syy);
        syy = fmaf(b[k].z, b[k].z, syy); syy = fmaf(b[k].w, b[k].w, syy);
    }

    sx  = warp_sum(sx);
    sy  = warp_sum(sy);
    sxy = warp_sum(sxy);
    sxx = warp_sum(sxx);
    syy = warp_sum(syy);

    __shared__ float sh[5][TPB / 32];
    __shared__ bool is_last;
    const int lane = threadIdx.x & 31;
    const int wid  = threadIdx.x >> 5;
    if (threadIdx.x == 0) is_last = false;
    if (lane == 0) {
        sh[0][wid] = sx;  sh[1][wid] = sy;  sh[2][wid] = sxy;
        sh[3][wid] = sxx; sh[4][wid] = syy;
    }
    __syncthreads();

    if (wid == 0) {
        const int nw = TPB / 32;
        float vx  = (lane < nw) ? sh[0][lane] : 0.f;
        float vy  = (lane < nw) ? sh[1][lane] : 0.f;
        float vxy = (lane < nw) ? sh[2][lane] : 0.f;
        float vxx = (lane < nw) ? sh[3][lane] : 0.f;
        float vyy = (lane < nw) ? sh[4][lane] : 0.f;
        #pragma unroll
        for (int off = 4; off > 0; off >>= 1) {
            vx  += __shfl_down_sync(0xffffffffu, vx,  off);
            vy  += __shfl_down_sync(0xffffffffu, vy,  off);
            vxy += __shfl_down_sync(0xffffffffu, vxy, off);
            vxx += __shfl_down_sync(0xffffffffu, vxx, off);
            vyy += __shfl_down_sync(0xffffffffu, vyy, off);
        }
        if (lane == 0) {
            float* slot = g_part[row][half];
            slot[0] = vx; slot[1] = vy; slot[2] = vxy;
            slot[3] = vxx; slot[4] = vyy;
            __threadfence();
            unsigned int r_old = atomicAdd(&g_row_ticket[row], 1u);
            if (r_old == 1u) {
                // Second arrival: both halves visible. Fixed combine order.
                const float* h0 = g_part[row][0];
                const float* h1 = g_part[row][1];
                float cx  = ldcg(h0 + 0) + ldcg(h1 + 0);
                float cy  = ldcg(h0 + 1) + ldcg(h1 + 1);
                float cxy = ldcg(h0 + 2) + ldcg(h1 + 2);
                float cxx = ldcg(h0 + 3) + ldcg(h1 + 3);
                float cyy = ldcg(h0 + 4) + ldcg(h1 + 4);
                const float Nf = (float)ROW_N;
                float num = Nf * cxy - cx * cy;
                float den = sqrtf((Nf * cxx - cx * cx) * (Nf * cyy - cy * cy));
                g_row_loss[row] = 1.0f - num / den;
                g_row_ticket[row] = 0u; // self-reset for next replay
                __threadfence();
                unsigned int old = atomicAdd(&g_ticket, 1u);
                is_last = (old == (unsigned int)(B - 1));
            }
        }
    }
    __syncthreads();

    if (!is_last) return;

    // Last row-winner CTA: vectorized fixed-order mean over row losses.
    float s = 0.f;
    const float4* rl = reinterpret_cast<const float4*>(g_row_loss);
    for (int i = threadIdx.x; i < B / 4; i += TPB) {
        float4 v;
        asm volatile("ld.global.cg.v4.f32 {%0,%1,%2,%3}, [%4];"
                     : "=f"(v.x), "=f"(v.y), "=f"(v.z), "=f"(v.w)
                     : "l"(rl + i));
        s += (v.x + v.y) + (v.z + v.w);
    }
    s = warp_sum(s);
    __shared__ float shf[TPB / 32];
    if (lane == 0) shf[wid] = s;
    __syncthreads();
    if (threadIdx.x == 0) {
        float t = 0.f;
        #pragma unroll
        for (int w = 0; w < TPB / 32; w++) t += shf[w];
        out[0] = t / (float)B;
        g_ticket = 0u; // reset for next graph replay
    }
}

extern "C" void kernel_launch(void* const* d_in, const int* in_sizes, int n_in,
                              void* d_out, int out_size) {
    const float* preds  = (const float*)d_in[0];
    const float* labels = (const float*)d_in[1];
    float* out = (float*)d_out;

    const int B = in_sizes[0] / ROW_N; // 4096
    np_half_kernel<<<B * 2, TPB>>>(preds, labels, out, B);
}